// round 1
// baseline (speedup 1.0000x reference)
#include <cuda_runtime.h>
#include <math.h>

// Problem dims (fixed by reference)
#define T_DIM 1024
#define B_DIM 16
#define H_DIM 1024
#define L_DIM 3
#define M_DIM (T_DIM * B_DIM)   // 16384 rows
#define N_DIM (3 * H_DIM)       // 3072 cols (z|f|o)
#define K_DIM H_DIM             // 1024

// Scratch (device globals — no runtime allocation allowed)
__device__ float g_h0[(size_t)M_DIM * H_DIM];   // 67 MB
__device__ float g_h1[(size_t)M_DIM * H_DIM];   // 67 MB
__device__ float g_G [(size_t)M_DIM * N_DIM];   // 201 MB

// ---------------------------------------------------------------------------
// Embedding gather: h[t,b,:] = emb[x[t,b],:]   (float4 vectorized)
// ---------------------------------------------------------------------------
__global__ void embed_kernel(const int* __restrict__ x,
                             const float* __restrict__ emb,
                             float* __restrict__ h)
{
    int idx = blockIdx.x * blockDim.x + threadIdx.x;   // over M*H/4
    int i   = idx * 4;
    int tb  = i >> 10;          // / H_DIM
    int hh  = i & (H_DIM - 1);
    int tok = x[tb];
    *(float4*)(h + i) = *(const float4*)(emb + (size_t)tok * H_DIM + hh);
}

// ---------------------------------------------------------------------------
// SGEMM + bias + fused gate activation.
//   C[M,N] = act( A[M,K] @ B[K,N] + bias[N] )
//   act: col <  H -> tanh (z); col >= H -> sigmoid (f, o)
// 128x128 tile, BK=8, 256 threads, 8x8 microtile.
// ---------------------------------------------------------------------------
__global__ __launch_bounds__(256, 2)
void gemm_act_kernel(const float* __restrict__ A,
                     const float* __restrict__ Bm,
                     const float* __restrict__ bias,
                     float* __restrict__ C)
{
    __shared__ float As[8][128];   // transposed A tile: As[k][m]
    __shared__ float Bs[8][128];   // Bs[k][n]

    const int tid = threadIdx.x;
    const int bm  = blockIdx.y * 128;
    const int bn  = blockIdx.x * 128;

    // A-tile load mapping: 128 rows x 8 cols, one float4 per thread
    const int a_row = tid >> 1;          // 0..127
    const int a_col = (tid & 1) * 4;     // 0 or 4
    // B-tile load mapping: 8 rows x 128 cols, one float4 per thread
    const int b_row = tid >> 5;          // 0..7
    const int b_col = (tid & 31) * 4;    // 0..124

    // Compute fragment mapping
    const int tx = (tid & 15) * 8;       // n offset within tile
    const int ty = (tid >> 4) * 8;       // m offset within tile

    const float* Aptr = A  + (size_t)(bm + a_row) * K_DIM + a_col;
    const float* Bptr = Bm + (size_t)b_row * N_DIM + bn + b_col;

    float acc[8][8];
    #pragma unroll
    for (int i = 0; i < 8; i++)
        #pragma unroll
        for (int j = 0; j < 8; j++) acc[i][j] = 0.0f;

    for (int k0 = 0; k0 < K_DIM; k0 += 8) {
        float4 av = *(const float4*)(Aptr + k0);
        As[a_col + 0][a_row] = av.x;
        As[a_col + 1][a_row] = av.y;
        As[a_col + 2][a_row] = av.z;
        As[a_col + 3][a_row] = av.w;
        *(float4*)&Bs[b_row][b_col] = *(const float4*)(Bptr + (size_t)k0 * N_DIM);
        __syncthreads();

        #pragma unroll
        for (int k = 0; k < 8; k++) {
            float a_frag[8], b_frag[8];
            *(float4*)&a_frag[0] = *(const float4*)&As[k][ty];
            *(float4*)&a_frag[4] = *(const float4*)&As[k][ty + 4];
            *(float4*)&b_frag[0] = *(const float4*)&Bs[k][tx];
            *(float4*)&b_frag[4] = *(const float4*)&Bs[k][tx + 4];
            #pragma unroll
            for (int i = 0; i < 8; i++)
                #pragma unroll
                for (int j = 0; j < 8; j++)
                    acc[i][j] = fmaf(a_frag[i], b_frag[j], acc[i][j]);
        }
        __syncthreads();
    }

    // Epilogue: bias + activation, write G
    #pragma unroll
    for (int i = 0; i < 8; i++) {
        const int row = bm + ty + i;
        #pragma unroll
        for (int j = 0; j < 8; j++) {
            const int col = bn + tx + j;
            float v = acc[i][j] + bias[col];
            if (col < H_DIM) v = tanhf(v);                  // z gate
            else             v = 1.0f / (1.0f + expf(-v));  // f / o gates
            C[(size_t)row * N_DIM + col] = v;
        }
    }
}

// ---------------------------------------------------------------------------
// Forget-mult scan + output gate.
//   c_t = f_t * z_t + (1 - f_t) * c_{t-1};  out_t = o_t * c_t  (t < Tout)
// One thread per (b, h) channel. Coalesced across h.
// ---------------------------------------------------------------------------
__global__ void scan_kernel(const float* __restrict__ G,
                            float* __restrict__ out, int Tout)
{
    const int j  = blockIdx.x * blockDim.x + threadIdx.x;  // 0 .. B*H-1
    const int b  = j >> 10;            // / H_DIM
    const int hh = j & (H_DIM - 1);

    const float* gz = G + (size_t)b * N_DIM + hh;
    float c = 0.0f;

    #pragma unroll 4
    for (int t = 0; t < T_DIM; t++) {
        const float* p = gz + (size_t)t * (B_DIM * N_DIM);
        float z = __ldg(p);
        float f = __ldg(p + H_DIM);
        float o = __ldg(p + 2 * H_DIM);
        c = f * z + (1.0f - f) * c;
        if (t < Tout)
            out[((size_t)t * B_DIM + b) * H_DIM + hh] = o * c;
    }
}

// ---------------------------------------------------------------------------
extern "C" void kernel_launch(void* const* d_in, const int* in_sizes, int n_in,
                              void* d_out, int out_size)
{
    const int*   x    = (const int*)  d_in[0];   // [T, B] int32
    const float* emb  = (const float*)d_in[1];   // [V, H]
    const float* W    = (const float*)d_in[2];   // [L, H, 3H]
    const float* bias = (const float*)d_in[3];   // [L, 3H]
    float* out = (float*)d_out;                  // [T-1, B, H]

    float *h0, *h1, *G;
    cudaGetSymbolAddress((void**)&h0, g_h0);
    cudaGetSymbolAddress((void**)&h1, g_h1);
    cudaGetSymbolAddress((void**)&G,  g_G);

    // 1) embedding gather
    {
        int total4 = (M_DIM * H_DIM) / 4;
        embed_kernel<<<total4 / 256, 256>>>(x, emb, h0);
    }

    dim3 gemm_grid(N_DIM / 128, M_DIM / 128);   // (24, 128)
    const int scan_blocks = (B_DIM * H_DIM) / 256;  // 64

    // layer 0: h0 -> G -> h1
    gemm_act_kernel<<<gemm_grid, 256>>>(h0, W + 0 * (size_t)K_DIM * N_DIM,
                                        bias + 0 * N_DIM, G);
    scan_kernel<<<scan_blocks, 256>>>(G, h1, T_DIM);

    // layer 1: h1 -> G -> h0
    gemm_act_kernel<<<gemm_grid, 256>>>(h1, W + 1 * (size_t)K_DIM * N_DIM,
                                        bias + 1 * N_DIM, G);
    scan_kernel<<<scan_blocks, 256>>>(G, h0, T_DIM);

    // layer 2: h0 -> G -> d_out (drop last timestep)
    gemm_act_kernel<<<gemm_grid, 256>>>(h0, W + 2 * (size_t)K_DIM * N_DIM,
                                        bias + 2 * N_DIM, G);
    scan_kernel<<<scan_blocks, 256>>>(G, out, T_DIM - 1);
}

// round 3
// speedup vs baseline: 2.7696x; 2.7696x over previous
#include <cuda_runtime.h>
#include <cstdint>
#include <math.h>

// Problem dims
#define T_DIM 1024
#define B_DIM 16
#define H_DIM 1024
#define L_DIM 3
#define M_DIM (T_DIM * B_DIM)   // 16384
#define N_DIM (3 * H_DIM)       // 3072
#define K_DIM H_DIM             // 1024

// GEMM tiling
#define BM 128
#define BN 128
#define BK 32
#define K_ITERS (K_DIM / BK)    // 32
#define WM 64                   // warp tile M  (warps: 2 x 4)
#define WN 32                   // warp tile N
#define MT (WM / 16)            // 4 mma tiles in M
#define NT (WN / 8)             // 4 mma tiles in N
#define ROWPAD 36               // floats per SMEM row (conflict-free quad access)
#define TILE_FLOATS (128 * ROWPAD)   // 4608 floats = 18432 B per tile buffer

// Scratch (device globals, no runtime alloc)
__device__ float g_h0[(size_t)M_DIM * H_DIM];
__device__ float g_h1[(size_t)M_DIM * H_DIM];
__device__ float g_G [(size_t)M_DIM * N_DIM];
__device__ float g_Wt[(size_t)L_DIM * N_DIM * K_DIM];  // W^T [L][N][K], tf32-rounded

// ---------------------------------------------------------------------------
// PTX helpers (sm_80-era only: mma.sync + cp.async — the compute_103 target
// rejects all tcgen05/TMEM instructions)
// ---------------------------------------------------------------------------
__device__ __forceinline__ uint32_t smem_to_u32(const void* p) {
    uint32_t a;
    asm("{ .reg .u64 t; cvta.to.shared.u64 t, %1; cvt.u32.u64 %0, t; }" : "=r"(a) : "l"(p));
    return a;
}
#define CP_ASYNC16(sa, gp) \
    asm volatile("cp.async.cg.shared.global [%0], [%1], 16;" :: "r"(sa), "l"(gp))
#define CP_COMMIT() asm volatile("cp.async.commit_group;" ::: "memory")
#define CP_WAIT1()  asm volatile("cp.async.wait_group 1;" ::: "memory")
#define CP_WAIT0()  asm volatile("cp.async.wait_group 0;" ::: "memory")

__device__ __forceinline__ void mma_tf32(float& c0, float& c1, float& c2, float& c3,
                                         uint32_t a0, uint32_t a1, uint32_t a2, uint32_t a3,
                                         uint32_t b0, uint32_t b1) {
    asm volatile("mma.sync.aligned.m16n8k8.row.col.f32.tf32.tf32.f32 "
                 "{%0,%1,%2,%3}, {%4,%5,%6,%7}, {%8,%9}, {%0,%1,%2,%3};"
                 : "+f"(c0), "+f"(c1), "+f"(c2), "+f"(c3)
                 : "r"(a0), "r"(a1), "r"(a2), "r"(a3), "r"(b0), "r"(b1));
}

__device__ __forceinline__ float to_tf32(float x) {
    float r;
    asm("cvt.rna.tf32.f32 %0, %1;" : "=f"(r) : "f"(x));
    return r;
}

// ---------------------------------------------------------------------------
// FMA-only activations (avoid MUFU pipe: 150M transcendentals would bind)
// ---------------------------------------------------------------------------
__device__ __forceinline__ float rcp_fma(float d) {
    float r = __int_as_float(0x7EF127EAu - __float_as_int(d));
    r = r * (2.0f - d * r);
    r = r * (2.0f - d * r);
    r = r * (2.0f - d * r);
    return r;
}
__device__ __forceinline__ float tanh_fast(float x) {
    x = fminf(fmaxf(x, -7.90531110f), 7.90531110f);
    float x2 = x * x;
    float p = -2.76076847742355e-16f;
    p = fmaf(p, x2, 2.00018790482477e-13f);
    p = fmaf(p, x2, -8.60467152213735e-11f);
    p = fmaf(p, x2, 5.12229709037114e-08f);
    p = fmaf(p, x2, 1.48572235717979e-05f);
    p = fmaf(p, x2, 6.37261928875436e-04f);
    p = fmaf(p, x2, 4.89352455891786e-03f);
    float q = 1.19825839466702e-06f;
    q = fmaf(q, x2, 1.18534705686654e-04f);
    q = fmaf(q, x2, 2.26843463243900e-03f);
    q = fmaf(q, x2, 4.89352518554385e-03f);
    return (x * p) * rcp_fma(q);
}
__device__ __forceinline__ float sigmoid_fast(float x) {
    return fmaf(0.5f, tanh_fast(0.5f * x), 0.5f);
}

// ---------------------------------------------------------------------------
// Embedding gather
// ---------------------------------------------------------------------------
__global__ void embed_kernel(const int* __restrict__ x,
                             const float* __restrict__ emb,
                             float* __restrict__ h)
{
    int idx = blockIdx.x * blockDim.x + threadIdx.x;
    int i   = idx * 4;
    int tb  = i >> 10;
    int hh  = i & (H_DIM - 1);
    int tok = x[tb];
    *(float4*)(h + i) = *(const float4*)(emb + (size_t)tok * H_DIM + hh);
}

// ---------------------------------------------------------------------------
// W transpose + tf32 round:  Wt[l][n][k] = tf32(W[l][k][n])
// ---------------------------------------------------------------------------
__global__ void transpose_kernel(const float* __restrict__ W, float* __restrict__ Wt)
{
    __shared__ float tile[32][33];
    int l  = blockIdx.z;
    int n0 = blockIdx.x * 32;
    int k0 = blockIdx.y * 32;
    int tx = threadIdx.x, ty = threadIdx.y;
    #pragma unroll
    for (int j = 0; j < 32; j += 8) {
        int k = k0 + ty + j, n = n0 + tx;
        tile[ty + j][tx] = to_tf32(W[((size_t)l * K_DIM + k) * N_DIM + n]);
    }
    __syncthreads();
    #pragma unroll
    for (int j = 0; j < 32; j += 8) {
        int n = n0 + ty + j, k = k0 + tx;
        Wt[((size_t)l * N_DIM + n) * K_DIM + k] = tile[tx][ty + j];
    }
}

// ---------------------------------------------------------------------------
// TF32 tensor-core GEMM (mma.sync) + bias + fused FMA-only activation
//   G[M,N] = act( A[M,K] @ Wt[N,K]^T + bias[N] )
// 128x128x32 CTA tile, 8 warps (2x4), double-buffered cp.async SMEM.
// ---------------------------------------------------------------------------
__global__ __launch_bounds__(256, 2)
void gemm_tc_kernel(const float* __restrict__ A,
                    const float* __restrict__ Bt,
                    const float* __restrict__ bias,
                    float* __restrict__ C)
{
    extern __shared__ float sm[];
    float* Abuf[2] = { sm,                sm + TILE_FLOATS };
    float* Bbuf[2] = { sm + 2*TILE_FLOATS, sm + 3*TILE_FLOATS };

    const int tid = threadIdx.x;
    const int wid = tid >> 5;
    const int lid = tid & 31;
    const int g   = lid >> 2;        // quad group (0..7)
    const int t   = lid & 3;         // thread-in-quad (0..3)
    const int bm  = blockIdx.y * BM;
    const int bn  = blockIdx.x * BN;
    const int wm  = (wid >> 2) * WM; // 0 or 64
    const int wn  = (wid & 3) * WN;  // 0,32,64,96

    // ---- loader mapping: 8 x 16B chunks per 32-float row; 256 threads cover
    // 32 rows per pass, 4 passes per 128-row tile.
    const int l_row = tid >> 3;      // 0..31
    const int l_cir = tid & 7;       // chunk-in-row
    const float* Ag = A  + (size_t)(bm + l_row) * K_DIM + l_cir * 4;
    const float* Bg = Bt + (size_t)(bn + l_row) * K_DIM + l_cir * 4;
    const uint32_t sAo = smem_to_u32(sm) + (l_row * ROWPAD + l_cir * 4) * 4;
    const uint32_t sBo = sAo + 2 * TILE_FLOATS * 4;

    float acc[MT][NT][4];
    #pragma unroll
    for (int i = 0; i < MT; i++)
        #pragma unroll
        for (int j = 0; j < NT; j++)
            #pragma unroll
            for (int r = 0; r < 4; r++) acc[i][j][r] = 0.0f;

    // ---- prologue: load chunk 0 into buffer 0
    {
        #pragma unroll
        for (int j = 0; j < 4; j++) {
            CP_ASYNC16(sAo + j * 32 * ROWPAD * 4, Ag + (size_t)(j * 32) * K_DIM);
            CP_ASYNC16(sBo + j * 32 * ROWPAD * 4, Bg + (size_t)(j * 32) * K_DIM);
        }
        CP_COMMIT();
    }

    for (int i = 0; i < K_ITERS; i++) {
        const int buf = i & 1;
        if (i + 1 < K_ITERS) {
            const uint32_t dA = sAo + (buf ^ 1) * TILE_FLOATS * 4;
            const uint32_t dB = sBo + (buf ^ 1) * TILE_FLOATS * 4;
            const float* Ak = Ag + (i + 1) * BK;
            const float* Bk = Bg + (i + 1) * BK;
            #pragma unroll
            for (int j = 0; j < 4; j++) {
                CP_ASYNC16(dA + j * 32 * ROWPAD * 4, Ak + (size_t)(j * 32) * K_DIM);
                CP_ASYNC16(dB + j * 32 * ROWPAD * 4, Bk + (size_t)(j * 32) * K_DIM);
            }
            CP_COMMIT();
            CP_WAIT1();
        } else {
            CP_WAIT0();
        }
        __syncthreads();

        const float* As = Abuf[buf];
        const float* Bs = Bbuf[buf];
        #pragma unroll
        for (int ks = 0; ks < 4; ks++) {
            const int kb = ks * 8;
            uint32_t af[MT][4], bf[NT][2];
            #pragma unroll
            for (int mt = 0; mt < MT; mt++) {
                const int m = wm + mt * 16 + g;
                af[mt][0] = __float_as_uint(As[(m    ) * ROWPAD + kb + t    ]);
                af[mt][1] = __float_as_uint(As[(m + 8) * ROWPAD + kb + t    ]);
                af[mt][2] = __float_as_uint(As[(m    ) * ROWPAD + kb + t + 4]);
                af[mt][3] = __float_as_uint(As[(m + 8) * ROWPAD + kb + t + 4]);
            }
            #pragma unroll
            for (int nt = 0; nt < NT; nt++) {
                const int n = wn + nt * 8 + g;
                bf[nt][0] = __float_as_uint(Bs[n * ROWPAD + kb + t    ]);
                bf[nt][1] = __float_as_uint(Bs[n * ROWPAD + kb + t + 4]);
            }
            #pragma unroll
            for (int mt = 0; mt < MT; mt++)
                #pragma unroll
                for (int nt = 0; nt < NT; nt++)
                    mma_tf32(acc[mt][nt][0], acc[mt][nt][1],
                             acc[mt][nt][2], acc[mt][nt][3],
                             af[mt][0], af[mt][1], af[mt][2], af[mt][3],
                             bf[nt][0], bf[nt][1]);
        }
        __syncthreads();
    }

    // ---- epilogue: bias + activation, float2 stores
    #pragma unroll
    for (int mt = 0; mt < MT; mt++) {
        const int row0 = bm + wm + mt * 16 + g;
        #pragma unroll
        for (int nt = 0; nt < NT; nt++) {
            const int col = bn + wn + nt * 8 + 2 * t;
            const float b0 = __ldg(&bias[col]);
            const float b1 = __ldg(&bias[col + 1]);
            float2 v0, v1;
            if (col < H_DIM) {   // z gate (8-wide tiles never straddle boundary)
                v0.x = tanh_fast(acc[mt][nt][0] + b0);
                v0.y = tanh_fast(acc[mt][nt][1] + b1);
                v1.x = tanh_fast(acc[mt][nt][2] + b0);
                v1.y = tanh_fast(acc[mt][nt][3] + b1);
            } else {             // f / o gates
                v0.x = sigmoid_fast(acc[mt][nt][0] + b0);
                v0.y = sigmoid_fast(acc[mt][nt][1] + b1);
                v1.x = sigmoid_fast(acc[mt][nt][2] + b0);
                v1.y = sigmoid_fast(acc[mt][nt][3] + b1);
            }
            *(float2*)&C[(size_t)row0 * N_DIM + col]       = v0;
            *(float2*)&C[(size_t)(row0 + 8) * N_DIM + col] = v1;
        }
    }
}

// ---------------------------------------------------------------------------
// Forget-mult scan + output gate
// ---------------------------------------------------------------------------
__global__ void scan_kernel(const float* __restrict__ G,
                            float* __restrict__ out, int Tout)
{
    const int j  = blockIdx.x * blockDim.x + threadIdx.x;
    const int b  = j >> 10;
    const int hh = j & (H_DIM - 1);
    const float* gz = G + (size_t)b * N_DIM + hh;
    float c = 0.0f;
    #pragma unroll 8
    for (int t = 0; t < T_DIM; t++) {
        const float* p = gz + (size_t)t * (B_DIM * N_DIM);
        float z = __ldg(p);
        float f = __ldg(p + H_DIM);
        float o = __ldg(p + 2 * H_DIM);
        c = fmaf(f, z - c, c);   // f*z + (1-f)*c
        if (t < Tout)
            out[((size_t)t * B_DIM + b) * H_DIM + hh] = o * c;
    }
}

// ---------------------------------------------------------------------------
#define SM_TOTAL (4 * TILE_FLOATS * 4)   // 73728 bytes

extern "C" void kernel_launch(void* const* d_in, const int* in_sizes, int n_in,
                              void* d_out, int out_size)
{
    const int*   x    = (const int*)  d_in[0];
    const float* emb  = (const float*)d_in[1];
    const float* W    = (const float*)d_in[2];
    const float* bias = (const float*)d_in[3];
    float* out = (float*)d_out;

    float *h0, *h1, *G, *Wt;
    cudaGetSymbolAddress((void**)&h0, g_h0);
    cudaGetSymbolAddress((void**)&h1, g_h1);
    cudaGetSymbolAddress((void**)&G,  g_G);
    cudaGetSymbolAddress((void**)&Wt, g_Wt);

    static bool attr_set = false;
    if (!attr_set) {
        cudaFuncSetAttribute(gemm_tc_kernel,
                             cudaFuncAttributeMaxDynamicSharedMemorySize, SM_TOTAL);
        attr_set = true;
    }

    embed_kernel<<<(M_DIM * H_DIM / 4) / 256, 256>>>(x, emb, h0);
    transpose_kernel<<<dim3(N_DIM / 32, K_DIM / 32, L_DIM), dim3(32, 8)>>>(W, Wt);

    dim3 ggrid(N_DIM / BN, M_DIM / BM);           // (24, 128)
    const int scan_grid = (B_DIM * H_DIM) / 128;  // 128 blocks x 128 threads

    gemm_tc_kernel<<<ggrid, 256, SM_TOTAL>>>(h0, Wt + 0 * (size_t)N_DIM * K_DIM,
                                             bias + 0 * N_DIM, G);
    scan_kernel<<<scan_grid, 128>>>(G, h1, T_DIM);

    gemm_tc_kernel<<<ggrid, 256, SM_TOTAL>>>(h1, Wt + 1 * (size_t)N_DIM * K_DIM,
                                             bias + 1 * N_DIM, G);
    scan_kernel<<<scan_grid, 128>>>(G, h0, T_DIM);

    gemm_tc_kernel<<<ggrid, 256, SM_TOTAL>>>(h0, Wt + 2 * (size_t)N_DIM * K_DIM,
                                             bias + 2 * N_DIM, G);
    scan_kernel<<<scan_grid, 128>>>(G, out, T_DIM - 1);
}

// round 4
// speedup vs baseline: 3.4973x; 1.2627x over previous
#include <cuda_runtime.h>
#include <cstdint>
#include <math.h>

// Problem dims
#define T_DIM 1024
#define B_DIM 16
#define H_DIM 1024
#define L_DIM 3
#define M_DIM (T_DIM * B_DIM)   // 16384
#define N_DIM (3 * H_DIM)       // 3072
#define K_DIM H_DIM             // 1024
#define NCH   (B_DIM * H_DIM)   // 16384 scan channels

// GEMM tiling
#define BM 128
#define BN 128
#define BK 32
#define K_ITERS (K_DIM / BK)    // 32
#define WM 64                   // warp tile M (warps 2 x 4)
#define WN 32                   // warp tile N
#define MT (WM / 16)
#define NT (WN / 8)
#define ROWPAD 36               // floats per SMEM row (conflict-free quad access)
#define TILE_FLOATS (128 * ROWPAD)      // 4608 floats per tile
#define STAGE_FLOATS (2 * TILE_FLOATS)  // A+B per stage = 9216 floats
#define STAGES 3
#define SM_TOTAL (STAGES * STAGE_FLOATS * 4)   // 110592 bytes

// Scan chunking
#define S_CHUNKS 8
#define CHUNK_T (T_DIM / S_CHUNKS)  // 128

// Scratch (device globals, no runtime alloc)
__device__ float g_h0[(size_t)M_DIM * H_DIM];
__device__ float g_h1[(size_t)M_DIM * H_DIM];
__device__ float g_G [(size_t)M_DIM * N_DIM];
__device__ float g_Wt[(size_t)L_DIM * N_DIM * K_DIM];
__device__ float g_P [(size_t)S_CHUNKS * NCH];
__device__ float g_Q [(size_t)S_CHUNKS * NCH];

// ---------------------------------------------------------------------------
// PTX helpers (sm_80-era only; compute_103 target rejects tcgen05)
// ---------------------------------------------------------------------------
__device__ __forceinline__ uint32_t smem_to_u32(const void* p) {
    uint32_t a;
    asm("{ .reg .u64 t; cvta.to.shared.u64 t, %1; cvt.u32.u64 %0, t; }" : "=r"(a) : "l"(p));
    return a;
}
#define CP_ASYNC16(sa, gp) \
    asm volatile("cp.async.cg.shared.global [%0], [%1], 16;" :: "r"(sa), "l"(gp))
#define CP_COMMIT() asm volatile("cp.async.commit_group;" ::: "memory")
#define CP_WAIT1()  asm volatile("cp.async.wait_group 1;" ::: "memory")
#define CP_WAIT0()  asm volatile("cp.async.wait_group 0;" ::: "memory")

__device__ __forceinline__ void mma_tf32(float& c0, float& c1, float& c2, float& c3,
                                         uint32_t a0, uint32_t a1, uint32_t a2, uint32_t a3,
                                         uint32_t b0, uint32_t b1) {
    asm volatile("mma.sync.aligned.m16n8k8.row.col.f32.tf32.tf32.f32 "
                 "{%0,%1,%2,%3}, {%4,%5,%6,%7}, {%8,%9}, {%0,%1,%2,%3};"
                 : "+f"(c0), "+f"(c1), "+f"(c2), "+f"(c3)
                 : "r"(a0), "r"(a1), "r"(a2), "r"(a3), "r"(b0), "r"(b1));
}
__device__ __forceinline__ float to_tf32(float x) {
    float r;
    asm("cvt.rna.tf32.f32 %0, %1;" : "=f"(r) : "f"(x));
    return r;
}

// ---------------------------------------------------------------------------
// FMA-only activations
// ---------------------------------------------------------------------------
__device__ __forceinline__ float rcp_fma(float d) {
    float r = __int_as_float(0x7EF127EAu - __float_as_int(d));
    r = r * (2.0f - d * r);
    r = r * (2.0f - d * r);
    r = r * (2.0f - d * r);
    return r;
}
__device__ __forceinline__ float tanh_fast(float x) {
    x = fminf(fmaxf(x, -7.90531110f), 7.90531110f);
    float x2 = x * x;
    float p = -2.76076847742355e-16f;
    p = fmaf(p, x2, 2.00018790482477e-13f);
    p = fmaf(p, x2, -8.60467152213735e-11f);
    p = fmaf(p, x2, 5.12229709037114e-08f);
    p = fmaf(p, x2, 1.48572235717979e-05f);
    p = fmaf(p, x2, 6.37261928875436e-04f);
    p = fmaf(p, x2, 4.89352455891786e-03f);
    float q = 1.19825839466702e-06f;
    q = fmaf(q, x2, 1.18534705686654e-04f);
    q = fmaf(q, x2, 2.26843463243900e-03f);
    q = fmaf(q, x2, 4.89352518554385e-03f);
    return (x * p) * rcp_fma(q);
}
__device__ __forceinline__ float sigmoid_fast(float x) {
    return fmaf(0.5f, tanh_fast(0.5f * x), 0.5f);
}

// ---------------------------------------------------------------------------
// Embedding gather
// ---------------------------------------------------------------------------
__global__ void embed_kernel(const int* __restrict__ x,
                             const float* __restrict__ emb,
                             float* __restrict__ h)
{
    int idx = blockIdx.x * blockDim.x + threadIdx.x;
    int i   = idx * 4;
    int tb  = i >> 10;
    int hh  = i & (H_DIM - 1);
    int tok = x[tb];
    *(float4*)(h + i) = *(const float4*)(emb + (size_t)tok * H_DIM + hh);
}

// ---------------------------------------------------------------------------
// W transpose + tf32 round:  Wt[l][n][k] = tf32(W[l][k][n])
// ---------------------------------------------------------------------------
__global__ void transpose_kernel(const float* __restrict__ W, float* __restrict__ Wt)
{
    __shared__ float tile[32][33];
    int l  = blockIdx.z;
    int n0 = blockIdx.x * 32;
    int k0 = blockIdx.y * 32;
    int tx = threadIdx.x, ty = threadIdx.y;
    #pragma unroll
    for (int j = 0; j < 32; j += 8) {
        int k = k0 + ty + j, n = n0 + tx;
        tile[ty + j][tx] = to_tf32(W[((size_t)l * K_DIM + k) * N_DIM + n]);
    }
    __syncthreads();
    #pragma unroll
    for (int j = 0; j < 32; j += 8) {
        int n = n0 + ty + j, k = k0 + tx;
        Wt[((size_t)l * N_DIM + n) * K_DIM + k] = tile[tx][ty + j];
    }
}

// ---------------------------------------------------------------------------
// TF32 tensor-core GEMM (mma.sync), 3-stage cp.async pipeline, 1 sync/iter.
//   G[M,N] = act( A[M,K] @ Wt[N,K]^T + bias[N] )
// ---------------------------------------------------------------------------
__global__ __launch_bounds__(256, 2)
void gemm_tc_kernel(const float* __restrict__ A,
                    const float* __restrict__ Bt,
                    const float* __restrict__ bias,
                    float* __restrict__ C)
{
    extern __shared__ float sm[];

    const int tid = threadIdx.x;
    const int wid = tid >> 5;
    const int lid = tid & 31;
    const int g   = lid >> 2;
    const int t   = lid & 3;
    const int bm  = blockIdx.y * BM;
    const int bn  = blockIdx.x * BN;
    const int wm  = (wid >> 2) * WM;
    const int wn  = (wid & 3) * WN;

    // loader mapping: 32 rows x 8 chunks per pass, 4 passes per tile
    const int l_row = tid >> 3;
    const int l_cir = tid & 7;
    const float* Ag = A  + (size_t)(bm + l_row) * K_DIM + l_cir * 4;
    const float* Bg = Bt + (size_t)(bn + l_row) * K_DIM + l_cir * 4;
    const uint32_t smem_base = smem_to_u32(sm);
    const uint32_t sAo = smem_base + (l_row * ROWPAD + l_cir * 4) * 4;
    const uint32_t sBo = sAo + TILE_FLOATS * 4;

    float acc[MT][NT][4];
    #pragma unroll
    for (int i = 0; i < MT; i++)
        #pragma unroll
        for (int j = 0; j < NT; j++)
            #pragma unroll
            for (int r = 0; r < 4; r++) acc[i][j][r] = 0.0f;

    // prologue: chunks 0,1 into stages 0,1
    #pragma unroll
    for (int p = 0; p < 2; p++) {
        const uint32_t soff = p * STAGE_FLOATS * 4;
        const float* Ak = Ag + p * BK;
        const float* Bk = Bg + p * BK;
        #pragma unroll
        for (int j = 0; j < 4; j++) {
            CP_ASYNC16(sAo + soff + j * 32 * ROWPAD * 4, Ak + (size_t)(j * 32) * K_DIM);
            CP_ASYNC16(sBo + soff + j * 32 * ROWPAD * 4, Bk + (size_t)(j * 32) * K_DIM);
        }
        CP_COMMIT();
    }

    int stg = 0;    // compute stage
    int wst = 2;    // write stage = (stg+2)%3
    for (int i = 0; i < K_ITERS; i++) {
        if (i + 1 < K_ITERS) CP_WAIT1(); else CP_WAIT0();
        __syncthreads();

        // issue chunk i+2 into write stage (also commits an empty group at tail
        // is unnecessary: waits above are conditioned on remaining groups)
        if (i + 2 < K_ITERS) {
            const uint32_t soff = wst * STAGE_FLOATS * 4;
            const float* Ak = Ag + (i + 2) * BK;
            const float* Bk = Bg + (i + 2) * BK;
            #pragma unroll
            for (int j = 0; j < 4; j++) {
                CP_ASYNC16(sAo + soff + j * 32 * ROWPAD * 4, Ak + (size_t)(j * 32) * K_DIM);
                CP_ASYNC16(sBo + soff + j * 32 * ROWPAD * 4, Bk + (size_t)(j * 32) * K_DIM);
            }
            CP_COMMIT();
        }

        const float* As = sm + stg * STAGE_FLOATS;
        const float* Bs = As + TILE_FLOATS;
        #pragma unroll
        for (int ks = 0; ks < 4; ks++) {
            const int kb = ks * 8;
            uint32_t af[MT][4], bf[NT][2];
            #pragma unroll
            for (int mt = 0; mt < MT; mt++) {
                const int m = wm + mt * 16 + g;
                af[mt][0] = __float_as_uint(As[(m    ) * ROWPAD + kb + t    ]);
                af[mt][1] = __float_as_uint(As[(m + 8) * ROWPAD + kb + t    ]);
                af[mt][2] = __float_as_uint(As[(m    ) * ROWPAD + kb + t + 4]);
                af[mt][3] = __float_as_uint(As[(m + 8) * ROWPAD + kb + t + 4]);
            }
            #pragma unroll
            for (int nt = 0; nt < NT; nt++) {
                const int n = wn + nt * 8 + g;
                bf[nt][0] = __float_as_uint(Bs[n * ROWPAD + kb + t    ]);
                bf[nt][1] = __float_as_uint(Bs[n * ROWPAD + kb + t + 4]);
            }
            #pragma unroll
            for (int mt = 0; mt < MT; mt++)
                #pragma unroll
                for (int nt = 0; nt < NT; nt++)
                    mma_tf32(acc[mt][nt][0], acc[mt][nt][1],
                             acc[mt][nt][2], acc[mt][nt][3],
                             af[mt][0], af[mt][1], af[mt][2], af[mt][3],
                             bf[nt][0], bf[nt][1]);
        }

        stg = (stg == 2) ? 0 : stg + 1;
        wst = (wst == 2) ? 0 : wst + 1;
    }

    // epilogue: bias + activation, float2 stores
    #pragma unroll
    for (int mt = 0; mt < MT; mt++) {
        const int row0 = bm + wm + mt * 16 + g;
        #pragma unroll
        for (int nt = 0; nt < NT; nt++) {
            const int col = bn + wn + nt * 8 + 2 * t;
            const float b0 = __ldg(&bias[col]);
            const float b1 = __ldg(&bias[col + 1]);
            float2 v0, v1;
            if (col < H_DIM) {
                v0.x = tanh_fast(acc[mt][nt][0] + b0);
                v0.y = tanh_fast(acc[mt][nt][1] + b1);
                v1.x = tanh_fast(acc[mt][nt][2] + b0);
                v1.y = tanh_fast(acc[mt][nt][3] + b1);
            } else {
                v0.x = sigmoid_fast(acc[mt][nt][0] + b0);
                v0.y = sigmoid_fast(acc[mt][nt][1] + b1);
                v1.x = sigmoid_fast(acc[mt][nt][2] + b0);
                v1.y = sigmoid_fast(acc[mt][nt][3] + b1);
            }
            *(float2*)&C[(size_t)row0 * N_DIM + col]       = v0;
            *(float2*)&C[(size_t)(row0 + 8) * N_DIM + col] = v1;
        }
    }
}

// ---------------------------------------------------------------------------
// Chunked-parallel forget-mult scan.
// Pass 1: per (chunk s, channel j), affine map of the chunk:
//   c_out = P*c_in + Q  with  P = prod(1-f),  Q = scan with c_in = 0.
// ---------------------------------------------------------------------------
__global__ void scan_pass1(const float* __restrict__ G,
                           float* __restrict__ P, float* __restrict__ Q)
{
    const int id = blockIdx.x * blockDim.x + threadIdx.x;   // 0 .. S*NCH-1
    const int j  = id & (NCH - 1);
    const int s  = id >> 14;
    const int b  = j >> 10;
    const int hh = j & (H_DIM - 1);
    const float* gz = G + (size_t)b * N_DIM + hh
                        + (size_t)(s * CHUNK_T) * (B_DIM * N_DIM);
    float c = 0.0f, p = 1.0f;
    #pragma unroll 4
    for (int t = 0; t < CHUNK_T; t++) {
        const float* ptr = gz + (size_t)t * (B_DIM * N_DIM);
        float z = __ldg(ptr);
        float f = __ldg(ptr + H_DIM);
        c = fmaf(f, z - c, c);
        p *= (1.0f - f);
    }
    P[id] = p;
    Q[id] = c;
}

// Pass 2: combine predecessor maps for the true chunk init, rescan, emit o*c.
__global__ void scan_pass2(const float* __restrict__ G,
                           const float* __restrict__ P, const float* __restrict__ Q,
                           float* __restrict__ out, int Tout)
{
    const int id = blockIdx.x * blockDim.x + threadIdx.x;
    const int j  = id & (NCH - 1);
    const int s  = id >> 14;
    const int b  = j >> 10;
    const int hh = j & (H_DIM - 1);

    float c = 0.0f;
    for (int ss = 0; ss < s; ss++)
        c = fmaf(__ldg(&P[ss * NCH + j]), c, __ldg(&Q[ss * NCH + j]));

    const float* gz = G + (size_t)b * N_DIM + hh
                        + (size_t)(s * CHUNK_T) * (B_DIM * N_DIM);
    float* ob = out + ((size_t)(s * CHUNK_T) * B_DIM + b) * H_DIM + hh;
    const int tmax = Tout - s * CHUNK_T;   // may exceed CHUNK_T (clamped below)
    #pragma unroll 4
    for (int t = 0; t < CHUNK_T; t++) {
        const float* ptr = gz + (size_t)t * (B_DIM * N_DIM);
        float z = __ldg(ptr);
        float f = __ldg(ptr + H_DIM);
        float o = __ldg(ptr + 2 * H_DIM);
        c = fmaf(f, z - c, c);
        if (t < tmax)
            ob[(size_t)t * (B_DIM * H_DIM)] = o * c;
    }
}

// ---------------------------------------------------------------------------
extern "C" void kernel_launch(void* const* d_in, const int* in_sizes, int n_in,
                              void* d_out, int out_size)
{
    const int*   x    = (const int*)  d_in[0];
    const float* emb  = (const float*)d_in[1];
    const float* W    = (const float*)d_in[2];
    const float* bias = (const float*)d_in[3];
    float* out = (float*)d_out;

    float *h0, *h1, *G, *Wt, *P, *Q;
    cudaGetSymbolAddress((void**)&h0, g_h0);
    cudaGetSymbolAddress((void**)&h1, g_h1);
    cudaGetSymbolAddress((void**)&G,  g_G);
    cudaGetSymbolAddress((void**)&Wt, g_Wt);
    cudaGetSymbolAddress((void**)&P,  g_P);
    cudaGetSymbolAddress((void**)&Q,  g_Q);

    static bool attr_set = false;
    if (!attr_set) {
        cudaFuncSetAttribute(gemm_tc_kernel,
                             cudaFuncAttributeMaxDynamicSharedMemorySize, SM_TOTAL);
        attr_set = true;
    }

    embed_kernel<<<(M_DIM * H_DIM / 4) / 256, 256>>>(x, emb, h0);
    transpose_kernel<<<dim3(N_DIM / 32, K_DIM / 32, L_DIM), dim3(32, 8)>>>(W, Wt);

    dim3 ggrid(N_DIM / BN, M_DIM / BM);                // (24, 128)
    const int sgrid = (S_CHUNKS * NCH) / 256;          // 512 blocks x 256

    gemm_tc_kernel<<<ggrid, 256, SM_TOTAL>>>(h0, Wt + 0 * (size_t)N_DIM * K_DIM,
                                             bias + 0 * N_DIM, G);
    scan_pass1<<<sgrid, 256>>>(G, P, Q);
    scan_pass2<<<sgrid, 256>>>(G, P, Q, h1, T_DIM);

    gemm_tc_kernel<<<ggrid, 256, SM_TOTAL>>>(h1, Wt + 1 * (size_t)N_DIM * K_DIM,
                                             bias + 1 * N_DIM, G);
    scan_pass1<<<sgrid, 256>>>(G, P, Q);
    scan_pass2<<<sgrid, 256>>>(G, P, Q, h0, T_DIM);

    gemm_tc_kernel<<<ggrid, 256, SM_TOTAL>>>(h0, Wt + 2 * (size_t)N_DIM * K_DIM,
                                             bias + 2 * N_DIM, G);
    scan_pass1<<<sgrid, 256>>>(G, P, Q);
    scan_pass2<<<sgrid, 256>>>(G, P, Q, out, T_DIM - 1);
}

// round 5
// speedup vs baseline: 5.3976x; 1.5434x over previous
#include <cuda_runtime.h>
#include <cuda_fp16.h>
#include <cstdint>
#include <math.h>

// Problem dims
#define T_DIM 1024
#define B_DIM 16
#define H_DIM 1024
#define L_DIM 3
#define M_DIM (T_DIM * B_DIM)   // 16384
#define N_DIM (3 * H_DIM)       // 3072
#define K_DIM H_DIM             // 1024
#define NCH   (B_DIM * H_DIM)   // 16384 scan channels

// GEMM tiling (fp16 operands, fp32 accum)
#define BM 128
#define BN 128
#define BK 64                    // halves per k-chunk
#define K_ITERS (K_DIM / BK)     // 16
#define WM 64                    // warp tile M (warps 2 x 4)
#define WN 32                    // warp tile N
#define MT (WM / 16)
#define NT (WN / 8)
#define ROWW 36                  // uint32 words per SMEM row (72 halves, padded)
#define TILE_WORDS (128 * ROWW)          // 4608 words = 18432 B
#define STAGE_WORDS (2 * TILE_WORDS)     // A+B per stage
#define STAGES 3
#define SM_TOTAL (STAGES * STAGE_WORDS * 4)   // 110592 bytes

// Scan chunking
#define S_CHUNKS 8
#define CHUNK_T (T_DIM / S_CHUNKS)  // 128

// Scratch (device globals, no runtime alloc)
__device__ __half g_h0[(size_t)M_DIM * H_DIM];
__device__ __half g_h1[(size_t)M_DIM * H_DIM];
__device__ float  g_G [(size_t)M_DIM * N_DIM];
__device__ __half g_Wt[(size_t)L_DIM * N_DIM * K_DIM];
__device__ float  g_P [(size_t)S_CHUNKS * NCH];
__device__ float  g_Q [(size_t)S_CHUNKS * NCH];

// ---------------------------------------------------------------------------
// PTX helpers (sm_80-era only; compute_103 target rejects tcgen05)
// ---------------------------------------------------------------------------
__device__ __forceinline__ uint32_t smem_to_u32(const void* p) {
    uint32_t a;
    asm("{ .reg .u64 t; cvta.to.shared.u64 t, %1; cvt.u32.u64 %0, t; }" : "=r"(a) : "l"(p));
    return a;
}
#define CP_ASYNC16(sa, gp) \
    asm volatile("cp.async.cg.shared.global [%0], [%1], 16;" :: "r"(sa), "l"(gp))
#define CP_COMMIT() asm volatile("cp.async.commit_group;" ::: "memory")
#define CP_WAIT1()  asm volatile("cp.async.wait_group 1;" ::: "memory")
#define CP_WAIT0()  asm volatile("cp.async.wait_group 0;" ::: "memory")

__device__ __forceinline__ void mma_f16(float& c0, float& c1, float& c2, float& c3,
                                        uint32_t a0, uint32_t a1, uint32_t a2, uint32_t a3,
                                        uint32_t b0, uint32_t b1) {
    asm volatile("mma.sync.aligned.m16n8k16.row.col.f32.f16.f16.f32 "
                 "{%0,%1,%2,%3}, {%4,%5,%6,%7}, {%8,%9}, {%0,%1,%2,%3};"
                 : "+f"(c0), "+f"(c1), "+f"(c2), "+f"(c3)
                 : "r"(a0), "r"(a1), "r"(a2), "r"(a3), "r"(b0), "r"(b1));
}

// ---------------------------------------------------------------------------
// FMA-only activations (avoid MUFU pipe)
// ---------------------------------------------------------------------------
__device__ __forceinline__ float rcp_fma(float d) {
    float r = __int_as_float(0x7EF127EAu - __float_as_int(d));
    r = r * (2.0f - d * r);
    r = r * (2.0f - d * r);
    r = r * (2.0f - d * r);
    return r;
}
__device__ __forceinline__ float tanh_fast(float x) {
    x = fminf(fmaxf(x, -7.90531110f), 7.90531110f);
    float x2 = x * x;
    float p = -2.76076847742355e-16f;
    p = fmaf(p, x2, 2.00018790482477e-13f);
    p = fmaf(p, x2, -8.60467152213735e-11f);
    p = fmaf(p, x2, 5.12229709037114e-08f);
    p = fmaf(p, x2, 1.48572235717979e-05f);
    p = fmaf(p, x2, 6.37261928875436e-04f);
    p = fmaf(p, x2, 4.89352455891786e-03f);
    float q = 1.19825839466702e-06f;
    q = fmaf(q, x2, 1.18534705686654e-04f);
    q = fmaf(q, x2, 2.26843463243900e-03f);
    q = fmaf(q, x2, 4.89352518554385e-03f);
    return (x * p) * rcp_fma(q);
}
__device__ __forceinline__ float sigmoid_fast(float x) {
    return fmaf(0.5f, tanh_fast(0.5f * x), 0.5f);
}

// ---------------------------------------------------------------------------
// Embedding gather -> fp16 h buffer
// ---------------------------------------------------------------------------
__global__ void embed_kernel(const int* __restrict__ x,
                             const float* __restrict__ emb,
                             __half* __restrict__ h)
{
    int idx = blockIdx.x * blockDim.x + threadIdx.x;
    int i   = idx * 4;
    int tb  = i >> 10;
    int hh  = i & (H_DIM - 1);
    int tok = x[tb];
    float4 v = *(const float4*)(emb + (size_t)tok * H_DIM + hh);
    __half2 lo = __floats2half2_rn(v.x, v.y);
    __half2 hi = __floats2half2_rn(v.z, v.w);
    uint2 pk = { *(uint32_t*)&lo, *(uint32_t*)&hi };
    *(uint2*)(h + i) = pk;
}

// ---------------------------------------------------------------------------
// W transpose + fp16 round:  Wt[l][n][k] = half(W[l][k][n])
// ---------------------------------------------------------------------------
__global__ void transpose_kernel(const float* __restrict__ W, __half* __restrict__ Wt)
{
    __shared__ float tile[32][33];
    int l  = blockIdx.z;
    int n0 = blockIdx.x * 32;
    int k0 = blockIdx.y * 32;
    int tx = threadIdx.x, ty = threadIdx.y;
    #pragma unroll
    for (int j = 0; j < 32; j += 8) {
        int k = k0 + ty + j, n = n0 + tx;
        tile[ty + j][tx] = W[((size_t)l * K_DIM + k) * N_DIM + n];
    }
    __syncthreads();
    #pragma unroll
    for (int j = 0; j < 32; j += 8) {
        int n = n0 + ty + j, k = k0 + tx;
        Wt[((size_t)l * N_DIM + n) * K_DIM + k] = __float2half_rn(tile[tx][ty + j]);
    }
}

// ---------------------------------------------------------------------------
// FP16 tensor-core GEMM (mma.sync m16n8k16), 3-stage cp.async pipeline.
//   G[M,N] = act( A[M,K] @ Wt[N,K]^T + bias[N] )   A, Wt fp16; accum fp32.
// ---------------------------------------------------------------------------
__global__ __launch_bounds__(256, 2)
void gemm_tc_kernel(const __half* __restrict__ A,
                    const __half* __restrict__ Bt,
                    const float* __restrict__ bias,
                    float* __restrict__ C)
{
    extern __shared__ uint32_t smw[];     // word view of SMEM

    const int tid = threadIdx.x;
    const int wid = tid >> 5;
    const int lid = tid & 31;
    const int g   = lid >> 2;
    const int t   = lid & 3;
    const int bm  = blockIdx.y * BM;
    const int bn  = blockIdx.x * BN;
    const int wm  = (wid >> 2) * WM;
    const int wn  = (wid & 3) * WN;

    // loader mapping: row 144B (72 halves of payload = 8 x 16B chunks + pad)
    const int l_row = tid >> 3;      // 0..31 (4 passes of 32 rows)
    const int l_cir = tid & 7;       // chunk-in-row
    const __half* Ag = A  + (size_t)(bm + l_row) * K_DIM + l_cir * 8;
    const __half* Bg = Bt + (size_t)(bn + l_row) * K_DIM + l_cir * 8;
    const uint32_t smem_base = smem_to_u32(smw);
    const uint32_t sAo = smem_base + l_row * 144 + l_cir * 16;
    const uint32_t sBo = sAo + TILE_WORDS * 4;

    float acc[MT][NT][4];
    #pragma unroll
    for (int i = 0; i < MT; i++)
        #pragma unroll
        for (int j = 0; j < NT; j++)
            #pragma unroll
            for (int r = 0; r < 4; r++) acc[i][j][r] = 0.0f;

    // prologue: k-chunks 0,1 into stages 0,1
    #pragma unroll
    for (int p = 0; p < 2; p++) {
        const uint32_t soff = p * STAGE_WORDS * 4;
        const __half* Ak = Ag + p * BK;
        const __half* Bk = Bg + p * BK;
        #pragma unroll
        for (int j = 0; j < 4; j++) {
            CP_ASYNC16(sAo + soff + j * 32 * 144, Ak + (size_t)(j * 32) * K_DIM);
            CP_ASYNC16(sBo + soff + j * 32 * 144, Bk + (size_t)(j * 32) * K_DIM);
        }
        CP_COMMIT();
    }

    int stg = 0, wst = 2;
    for (int i = 0; i < K_ITERS; i++) {
        if (i + 1 < K_ITERS) CP_WAIT1(); else CP_WAIT0();
        __syncthreads();

        if (i + 2 < K_ITERS) {
            const uint32_t soff = wst * STAGE_WORDS * 4;
            const __half* Ak = Ag + (i + 2) * BK;
            const __half* Bk = Bg + (i + 2) * BK;
            #pragma unroll
            for (int j = 0; j < 4; j++) {
                CP_ASYNC16(sAo + soff + j * 32 * 144, Ak + (size_t)(j * 32) * K_DIM);
                CP_ASYNC16(sBo + soff + j * 32 * 144, Bk + (size_t)(j * 32) * K_DIM);
            }
            CP_COMMIT();
        }

        const uint32_t* As32 = smw + stg * STAGE_WORDS;
        const uint32_t* Bs32 = As32 + TILE_WORDS;
        #pragma unroll
        for (int ks = 0; ks < 4; ks++) {          // 4 k16 steps per 64-half chunk
            const int kw = ks * 8;                // word offset in row
            uint32_t af[MT][4], bf[NT][2];
            #pragma unroll
            for (int mt = 0; mt < MT; mt++) {
                const int m = wm + mt * 16 + g;
                af[mt][0] = As32[(m    ) * ROWW + kw + t    ];
                af[mt][1] = As32[(m + 8) * ROWW + kw + t    ];
                af[mt][2] = As32[(m    ) * ROWW + kw + t + 4];
                af[mt][3] = As32[(m + 8) * ROWW + kw + t + 4];
            }
            #pragma unroll
            for (int nt = 0; nt < NT; nt++) {
                const int n = wn + nt * 8 + g;
                bf[nt][0] = Bs32[n * ROWW + kw + t    ];
                bf[nt][1] = Bs32[n * ROWW + kw + t + 4];
            }
            #pragma unroll
            for (int mt = 0; mt < MT; mt++)
                #pragma unroll
                for (int nt = 0; nt < NT; nt++)
                    mma_f16(acc[mt][nt][0], acc[mt][nt][1],
                            acc[mt][nt][2], acc[mt][nt][3],
                            af[mt][0], af[mt][1], af[mt][2], af[mt][3],
                            bf[nt][0], bf[nt][1]);
        }

        stg = (stg == 2) ? 0 : stg + 1;
        wst = (wst == 2) ? 0 : wst + 1;
    }

    // epilogue: bias + activation, float2 stores (G stays fp32)
    #pragma unroll
    for (int mt = 0; mt < MT; mt++) {
        const int row0 = bm + wm + mt * 16 + g;
        #pragma unroll
        for (int nt = 0; nt < NT; nt++) {
            const int col = bn + wn + nt * 8 + 2 * t;
            const float b0 = __ldg(&bias[col]);
            const float b1 = __ldg(&bias[col + 1]);
            float2 v0, v1;
            if (col < H_DIM) {
                v0.x = tanh_fast(acc[mt][nt][0] + b0);
                v0.y = tanh_fast(acc[mt][nt][1] + b1);
                v1.x = tanh_fast(acc[mt][nt][2] + b0);
                v1.y = tanh_fast(acc[mt][nt][3] + b1);
            } else {
                v0.x = sigmoid_fast(acc[mt][nt][0] + b0);
                v0.y = sigmoid_fast(acc[mt][nt][1] + b1);
                v1.x = sigmoid_fast(acc[mt][nt][2] + b0);
                v1.y = sigmoid_fast(acc[mt][nt][3] + b1);
            }
            *(float2*)&C[(size_t)row0 * N_DIM + col]       = v0;
            *(float2*)&C[(size_t)(row0 + 8) * N_DIM + col] = v1;
        }
    }
}

// ---------------------------------------------------------------------------
// Chunked-parallel forget-mult scan (pass1: per-chunk affine map P,Q)
// ---------------------------------------------------------------------------
__global__ void scan_pass1(const float* __restrict__ G,
                           float* __restrict__ P, float* __restrict__ Q)
{
    const int id = blockIdx.x * blockDim.x + threadIdx.x;
    const int j  = id & (NCH - 1);
    const int s  = id >> 14;
    const int b  = j >> 10;
    const int hh = j & (H_DIM - 1);
    const float* gz = G + (size_t)b * N_DIM + hh
                        + (size_t)(s * CHUNK_T) * (B_DIM * N_DIM);
    float c = 0.0f, p = 1.0f;
    #pragma unroll 4
    for (int t = 0; t < CHUNK_T; t++) {
        const float* ptr = gz + (size_t)t * (B_DIM * N_DIM);
        float z = __ldg(ptr);
        float f = __ldg(ptr + H_DIM);
        c = fmaf(f, z - c, c);
        p *= (1.0f - f);
    }
    P[id] = p;
    Q[id] = c;
}

// pass2: combine predecessor maps, rescan, emit o*c (half for next layer,
// float for final output).
__global__ void scan_pass2(const float* __restrict__ G,
                           const float* __restrict__ P, const float* __restrict__ Q,
                           float* __restrict__ outf, __half* __restrict__ outh,
                           int Tout, int write_half)
{
    const int id = blockIdx.x * blockDim.x + threadIdx.x;
    const int j  = id & (NCH - 1);
    const int s  = id >> 14;
    const int b  = j >> 10;
    const int hh = j & (H_DIM - 1);

    float c = 0.0f;
    for (int ss = 0; ss < s; ss++)
        c = fmaf(__ldg(&P[ss * NCH + j]), c, __ldg(&Q[ss * NCH + j]));

    const float* gz = G + (size_t)b * N_DIM + hh
                        + (size_t)(s * CHUNK_T) * (B_DIM * N_DIM);
    const size_t obase = ((size_t)(s * CHUNK_T) * B_DIM + b) * H_DIM + hh;
    const int tmax = Tout - s * CHUNK_T;
    #pragma unroll 4
    for (int t = 0; t < CHUNK_T; t++) {
        const float* ptr = gz + (size_t)t * (B_DIM * N_DIM);
        float z = __ldg(ptr);
        float f = __ldg(ptr + H_DIM);
        float o = __ldg(ptr + 2 * H_DIM);
        c = fmaf(f, z - c, c);
        if (t < tmax) {
            float v = o * c;
            if (write_half)
                outh[obase + (size_t)t * (B_DIM * H_DIM)] = __float2half_rn(v);
            else
                outf[obase + (size_t)t * (B_DIM * H_DIM)] = v;
        }
    }
}

// ---------------------------------------------------------------------------
extern "C" void kernel_launch(void* const* d_in, const int* in_sizes, int n_in,
                              void* d_out, int out_size)
{
    const int*   x    = (const int*)  d_in[0];
    const float* emb  = (const float*)d_in[1];
    const float* W    = (const float*)d_in[2];
    const float* bias = (const float*)d_in[3];
    float* out = (float*)d_out;

    __half *h0, *h1, *Wt;
    float *G, *P, *Q;
    cudaGetSymbolAddress((void**)&h0, g_h0);
    cudaGetSymbolAddress((void**)&h1, g_h1);
    cudaGetSymbolAddress((void**)&G,  g_G);
    cudaGetSymbolAddress((void**)&Wt, g_Wt);
    cudaGetSymbolAddress((void**)&P,  g_P);
    cudaGetSymbolAddress((void**)&Q,  g_Q);

    static bool attr_set = false;
    if (!attr_set) {
        cudaFuncSetAttribute(gemm_tc_kernel,
                             cudaFuncAttributeMaxDynamicSharedMemorySize, SM_TOTAL);
        attr_set = true;
    }

    embed_kernel<<<(M_DIM * H_DIM / 4) / 256, 256>>>(x, emb, h0);
    transpose_kernel<<<dim3(N_DIM / 32, K_DIM / 32, L_DIM), dim3(32, 8)>>>(W, Wt);

    dim3 ggrid(N_DIM / BN, M_DIM / BM);                // (24, 128)
    const int sgrid = (S_CHUNKS * NCH) / 256;          // 512 blocks x 256

    gemm_tc_kernel<<<ggrid, 256, SM_TOTAL>>>(h0, Wt + 0 * (size_t)N_DIM * K_DIM,
                                             bias + 0 * N_DIM, G);
    scan_pass1<<<sgrid, 256>>>(G, P, Q);
    scan_pass2<<<sgrid, 256>>>(G, P, Q, nullptr, h1, T_DIM, 1);

    gemm_tc_kernel<<<ggrid, 256, SM_TOTAL>>>(h1, Wt + 1 * (size_t)N_DIM * K_DIM,
                                             bias + 1 * N_DIM, G);
    scan_pass1<<<sgrid, 256>>>(G, P, Q);
    scan_pass2<<<sgrid, 256>>>(G, P, Q, nullptr, h0, T_DIM, 1);

    gemm_tc_kernel<<<ggrid, 256, SM_TOTAL>>>(h0, Wt + 2 * (size_t)N_DIM * K_DIM,
                                             bias + 2 * N_DIM, G);
    scan_pass1<<<sgrid, 256>>>(G, P, Q);
    scan_pass2<<<sgrid, 256>>>(G, P, Q, out, nullptr, T_DIM - 1, 0);
}

// round 6
// speedup vs baseline: 5.6668x; 1.0499x over previous
#include <cuda_runtime.h>
#include <cuda_fp16.h>
#include <cstdint>
#include <math.h>

// Problem dims
#define T_DIM 1024
#define B_DIM 16
#define H_DIM 1024
#define L_DIM 3
#define M_DIM (T_DIM * B_DIM)   // 16384
#define N_DIM (3 * H_DIM)       // 3072
#define K_DIM H_DIM             // 1024
#define NCH   (B_DIM * H_DIM)   // 16384 scan channels

// GEMM tiling (fp16 operands, fp32 accum)
#define BM 128
#define BN 128
#define BK 64                    // halves per k-chunk
#define K_ITERS (K_DIM / BK)     // 16
#define WM 64                    // warp tile M (warps 2 x 4)
#define WN 32                    // warp tile N
#define MT (WM / 16)
#define NT (WN / 8)
#define ROWB 144                 // bytes per SMEM row (72 halves, padded)
#define TILE_BYTES (128 * ROWB)            // 18432 B per tile
#define STAGE_BYTES (2 * TILE_BYTES)       // A+B per stage
#define STAGES 3
#define SM_TOTAL (STAGES * STAGE_BYTES)    // 110592 bytes

// Scan chunking
#define S_CHUNKS 8
#define CHUNK_T (T_DIM / S_CHUNKS)  // 128

// Scratch (device globals, no runtime alloc)
__device__ __half g_h0[(size_t)M_DIM * H_DIM];
__device__ __half g_h1[(size_t)M_DIM * H_DIM];
__device__ float  g_G [(size_t)M_DIM * N_DIM];
__device__ __half g_Wt[(size_t)L_DIM * N_DIM * K_DIM];
__device__ float  g_P [(size_t)S_CHUNKS * NCH];
__device__ float  g_Q [(size_t)S_CHUNKS * NCH];

// ---------------------------------------------------------------------------
// PTX helpers (sm_80-era only; compute_103 target rejects tcgen05)
// ---------------------------------------------------------------------------
__device__ __forceinline__ uint32_t smem_to_u32(const void* p) {
    uint32_t a;
    asm("{ .reg .u64 t; cvta.to.shared.u64 t, %1; cvt.u32.u64 %0, t; }" : "=r"(a) : "l"(p));
    return a;
}
#define CP_ASYNC16(sa, gp) \
    asm volatile("cp.async.cg.shared.global [%0], [%1], 16;" :: "r"(sa), "l"(gp))
#define CP_COMMIT() asm volatile("cp.async.commit_group;" ::: "memory")
#define CP_WAIT1()  asm volatile("cp.async.wait_group 1;" ::: "memory")
#define CP_WAIT0()  asm volatile("cp.async.wait_group 0;" ::: "memory")

#define LDSM_X4(r0, r1, r2, r3, addr) \
    asm volatile("ldmatrix.sync.aligned.m8n8.x4.shared.b16 {%0,%1,%2,%3}, [%4];" \
                 : "=r"(r0), "=r"(r1), "=r"(r2), "=r"(r3) : "r"(addr))

__device__ __forceinline__ void mma_f16(float& c0, float& c1, float& c2, float& c3,
                                        uint32_t a0, uint32_t a1, uint32_t a2, uint32_t a3,
                                        uint32_t b0, uint32_t b1) {
    asm volatile("mma.sync.aligned.m16n8k16.row.col.f32.f16.f16.f32 "
                 "{%0,%1,%2,%3}, {%4,%5,%6,%7}, {%8,%9}, {%0,%1,%2,%3};"
                 : "+f"(c0), "+f"(c1), "+f"(c2), "+f"(c3)
                 : "r"(a0), "r"(a1), "r"(a2), "r"(a3), "r"(b0), "r"(b1));
}

// ---------------------------------------------------------------------------
// FMA-only activations (avoid MUFU pipe)
// ---------------------------------------------------------------------------
__device__ __forceinline__ float rcp_fma(float d) {
    float r = __int_as_float(0x7EF127EAu - __float_as_int(d));
    r = r * (2.0f - d * r);
    r = r * (2.0f - d * r);
    r = r * (2.0f - d * r);
    return r;
}
__device__ __forceinline__ float tanh_fast(float x) {
    x = fminf(fmaxf(x, -7.90531110f), 7.90531110f);
    float x2 = x * x;
    float p = -2.76076847742355e-16f;
    p = fmaf(p, x2, 2.00018790482477e-13f);
    p = fmaf(p, x2, -8.60467152213735e-11f);
    p = fmaf(p, x2, 5.12229709037114e-08f);
    p = fmaf(p, x2, 1.48572235717979e-05f);
    p = fmaf(p, x2, 6.37261928875436e-04f);
    p = fmaf(p, x2, 4.89352455891786e-03f);
    float q = 1.19825839466702e-06f;
    q = fmaf(q, x2, 1.18534705686654e-04f);
    q = fmaf(q, x2, 2.26843463243900e-03f);
    q = fmaf(q, x2, 4.89352518554385e-03f);
    return (x * p) * rcp_fma(q);
}
__device__ __forceinline__ float sigmoid_fast(float x) {
    return fmaf(0.5f, tanh_fast(0.5f * x), 0.5f);
}

// ---------------------------------------------------------------------------
// Embedding gather -> fp16 h buffer
// ---------------------------------------------------------------------------
__global__ void embed_kernel(const int* __restrict__ x,
                             const float* __restrict__ emb,
                             __half* __restrict__ h)
{
    int idx = blockIdx.x * blockDim.x + threadIdx.x;
    int i   = idx * 4;
    int tb  = i >> 10;
    int hh  = i & (H_DIM - 1);
    int tok = x[tb];
    float4 v = *(const float4*)(emb + (size_t)tok * H_DIM + hh);
    __half2 lo = __floats2half2_rn(v.x, v.y);
    __half2 hi = __floats2half2_rn(v.z, v.w);
    uint2 pk = { *(uint32_t*)&lo, *(uint32_t*)&hi };
    *(uint2*)(h + i) = pk;
}

// ---------------------------------------------------------------------------
// W transpose + fp16 round:  Wt[l][n][k] = half(W[l][k][n])
// ---------------------------------------------------------------------------
__global__ void transpose_kernel(const float* __restrict__ W, __half* __restrict__ Wt)
{
    __shared__ float tile[32][33];
    int l  = blockIdx.z;
    int n0 = blockIdx.x * 32;
    int k0 = blockIdx.y * 32;
    int tx = threadIdx.x, ty = threadIdx.y;
    #pragma unroll
    for (int j = 0; j < 32; j += 8) {
        int k = k0 + ty + j, n = n0 + tx;
        tile[ty + j][tx] = W[((size_t)l * K_DIM + k) * N_DIM + n];
    }
    __syncthreads();
    #pragma unroll
    for (int j = 0; j < 32; j += 8) {
        int n = n0 + ty + j, k = k0 + tx;
        Wt[((size_t)l * N_DIM + n) * K_DIM + k] = __float2half_rn(tile[tx][ty + j]);
    }
}

// ---------------------------------------------------------------------------
// FP16 tensor-core GEMM: mma.sync m16n8k16 + ldmatrix + 3-stage cp.async.
//   G[M,N] = act( A[M,K] @ Wt[N,K]^T + bias[N] )
// ---------------------------------------------------------------------------
__global__ __launch_bounds__(256, 2)
void gemm_tc_kernel(const __half* __restrict__ A,
                    const __half* __restrict__ Bt,
                    const float* __restrict__ bias,
                    float* __restrict__ C)
{
    extern __shared__ char smem[];

    const int tid = threadIdx.x;
    const int wid = tid >> 5;
    const int lid = tid & 31;
    const int g   = lid >> 2;
    const int t   = lid & 3;
    const int bm  = blockIdx.y * BM;
    const int bn  = blockIdx.x * BN;
    const int wm  = (wid >> 2) * WM;
    const int wn  = (wid & 3) * WN;

    // loader mapping: 32 rows x 8 x 16B chunks per pass, 4 passes per tile
    const int l_row = tid >> 3;
    const int l_cir = tid & 7;
    const __half* Ag = A  + (size_t)(bm + l_row) * K_DIM + l_cir * 8;
    const __half* Bg = Bt + (size_t)(bn + l_row) * K_DIM + l_cir * 8;
    const uint32_t smem_base = smem_to_u32(smem);
    const uint32_t sAo = smem_base + l_row * ROWB + l_cir * 16;
    const uint32_t sBo = sAo + TILE_BYTES;

    // ldmatrix address offsets (relative to stage base)
    const int r8 = lid & 7;
    const int q  = lid >> 3;
    uint32_t aoff[MT], boff[NT / 2];
    #pragma unroll
    for (int mt = 0; mt < MT; mt++)
        aoff[mt] = (uint32_t)((wm + mt * 16 + r8 + (q & 1) * 8) * ROWB + (q >> 1) * 16);
    #pragma unroll
    for (int p = 0; p < NT / 2; p++)
        boff[p] = (uint32_t)(TILE_BYTES + (wn + p * 16 + r8 + (q >> 1) * 8) * ROWB
                             + (q & 1) * 16);

    float acc[MT][NT][4];
    #pragma unroll
    for (int i = 0; i < MT; i++)
        #pragma unroll
        for (int j = 0; j < NT; j++)
            #pragma unroll
            for (int r = 0; r < 4; r++) acc[i][j][r] = 0.0f;

    // prologue: k-chunks 0,1 into stages 0,1
    #pragma unroll
    for (int p = 0; p < 2; p++) {
        const uint32_t soff = p * STAGE_BYTES;
        const __half* Ak = Ag + p * BK;
        const __half* Bk = Bg + p * BK;
        #pragma unroll
        for (int j = 0; j < 4; j++) {
            CP_ASYNC16(sAo + soff + j * 32 * ROWB, Ak + (size_t)(j * 32) * K_DIM);
            CP_ASYNC16(sBo + soff + j * 32 * ROWB, Bk + (size_t)(j * 32) * K_DIM);
        }
        CP_COMMIT();
    }

    int stg = 0, wst = 2;
    for (int i = 0; i < K_ITERS; i++) {
        if (i + 1 < K_ITERS) CP_WAIT1(); else CP_WAIT0();
        __syncthreads();

        if (i + 2 < K_ITERS) {
            const uint32_t soff = wst * STAGE_BYTES;
            const __half* Ak = Ag + (i + 2) * BK;
            const __half* Bk = Bg + (i + 2) * BK;
            #pragma unroll
            for (int j = 0; j < 4; j++) {
                CP_ASYNC16(sAo + soff + j * 32 * ROWB, Ak + (size_t)(j * 32) * K_DIM);
                CP_ASYNC16(sBo + soff + j * 32 * ROWB, Bk + (size_t)(j * 32) * K_DIM);
            }
            CP_COMMIT();
        }

        const uint32_t sbase = smem_base + stg * STAGE_BYTES;
        #pragma unroll
        for (int ks = 0; ks < 4; ks++) {          // 4 k16 steps per 64-half chunk
            const uint32_t kb = ks * 32;          // byte offset along k
            uint32_t af[MT][4], bf[NT][2];
            #pragma unroll
            for (int mt = 0; mt < MT; mt++)
                LDSM_X4(af[mt][0], af[mt][1], af[mt][2], af[mt][3],
                        sbase + aoff[mt] + kb);
            #pragma unroll
            for (int p = 0; p < NT / 2; p++)
                LDSM_X4(bf[2 * p][0], bf[2 * p][1], bf[2 * p + 1][0], bf[2 * p + 1][1],
                        sbase + boff[p] + kb);
            #pragma unroll
            for (int mt = 0; mt < MT; mt++)
                #pragma unroll
                for (int nt = 0; nt < NT; nt++)
                    mma_f16(acc[mt][nt][0], acc[mt][nt][1],
                            acc[mt][nt][2], acc[mt][nt][3],
                            af[mt][0], af[mt][1], af[mt][2], af[mt][3],
                            bf[nt][0], bf[nt][1]);
        }

        stg = (stg == 2) ? 0 : stg + 1;
        wst = (wst == 2) ? 0 : wst + 1;
    }

    // epilogue: bias + activation, float2 stores (G stays fp32)
    #pragma unroll
    for (int mt = 0; mt < MT; mt++) {
        const int row0 = bm + wm + mt * 16 + g;
        #pragma unroll
        for (int nt = 0; nt < NT; nt++) {
            const int col = bn + wn + nt * 8 + 2 * t;
            const float b0 = __ldg(&bias[col]);
            const float b1 = __ldg(&bias[col + 1]);
            float2 v0, v1;
            if (col < H_DIM) {
                v0.x = tanh_fast(acc[mt][nt][0] + b0);
                v0.y = tanh_fast(acc[mt][nt][1] + b1);
                v1.x = tanh_fast(acc[mt][nt][2] + b0);
                v1.y = tanh_fast(acc[mt][nt][3] + b1);
            } else {
                v0.x = sigmoid_fast(acc[mt][nt][0] + b0);
                v0.y = sigmoid_fast(acc[mt][nt][1] + b1);
                v1.x = sigmoid_fast(acc[mt][nt][2] + b0);
                v1.y = sigmoid_fast(acc[mt][nt][3] + b1);
            }
            *(float2*)&C[(size_t)row0 * N_DIM + col]       = v0;
            *(float2*)&C[(size_t)(row0 + 8) * N_DIM + col] = v1;
        }
    }
}

// ---------------------------------------------------------------------------
// Chunked-parallel forget-mult scan (pass1: per-chunk affine map P,Q)
// ---------------------------------------------------------------------------
__global__ void scan_pass1(const float* __restrict__ G,
                           float* __restrict__ P, float* __restrict__ Q)
{
    const int id = blockIdx.x * blockDim.x + threadIdx.x;
    const int j  = id & (NCH - 1);
    const int s  = id >> 14;
    const int b  = j >> 10;
    const int hh = j & (H_DIM - 1);
    const float* gz = G + (size_t)b * N_DIM + hh
                        + (size_t)(s * CHUNK_T) * (B_DIM * N_DIM);
    float c = 0.0f, p = 1.0f;
    #pragma unroll 4
    for (int t = 0; t < CHUNK_T; t++) {
        const float* ptr = gz + (size_t)t * (B_DIM * N_DIM);
        float z = __ldg(ptr);
        float f = __ldg(ptr + H_DIM);
        c = fmaf(f, z - c, c);
        p *= (1.0f - f);
    }
    P[id] = p;
    Q[id] = c;
}

// pass2: combine predecessor maps, rescan, emit o*c
__global__ void scan_pass2(const float* __restrict__ G,
                           const float* __restrict__ P, const float* __restrict__ Q,
                           float* __restrict__ outf, __half* __restrict__ outh,
                           int Tout, int write_half)
{
    const int id = blockIdx.x * blockDim.x + threadIdx.x;
    const int j  = id & (NCH - 1);
    const int s  = id >> 14;
    const int b  = j >> 10;
    const int hh = j & (H_DIM - 1);

    float c = 0.0f;
    for (int ss = 0; ss < s; ss++)
        c = fmaf(__ldg(&P[ss * NCH + j]), c, __ldg(&Q[ss * NCH + j]));

    const float* gz = G + (size_t)b * N_DIM + hh
                        + (size_t)(s * CHUNK_T) * (B_DIM * N_DIM);
    const size_t obase = ((size_t)(s * CHUNK_T) * B_DIM + b) * H_DIM + hh;
    const int tmax = Tout - s * CHUNK_T;
    #pragma unroll 4
    for (int t = 0; t < CHUNK_T; t++) {
        const float* ptr = gz + (size_t)t * (B_DIM * N_DIM);
        float z = __ldg(ptr);
        float f = __ldg(ptr + H_DIM);
        float o = __ldg(ptr + 2 * H_DIM);
        c = fmaf(f, z - c, c);
        if (t < tmax) {
            float v = o * c;
            if (write_half)
                outh[obase + (size_t)t * (B_DIM * H_DIM)] = __float2half_rn(v);
            else
                outf[obase + (size_t)t * (B_DIM * H_DIM)] = v;
        }
    }
}

// ---------------------------------------------------------------------------
extern "C" void kernel_launch(void* const* d_in, const int* in_sizes, int n_in,
                              void* d_out, int out_size)
{
    const int*   x    = (const int*)  d_in[0];
    const float* emb  = (const float*)d_in[1];
    const float* W    = (const float*)d_in[2];
    const float* bias = (const float*)d_in[3];
    float* out = (float*)d_out;

    __half *h0, *h1, *Wt;
    float *G, *P, *Q;
    cudaGetSymbolAddress((void**)&h0, g_h0);
    cudaGetSymbolAddress((void**)&h1, g_h1);
    cudaGetSymbolAddress((void**)&G,  g_G);
    cudaGetSymbolAddress((void**)&Wt, g_Wt);
    cudaGetSymbolAddress((void**)&P,  g_P);
    cudaGetSymbolAddress((void**)&Q,  g_Q);

    static bool attr_set = false;
    if (!attr_set) {
        cudaFuncSetAttribute(gemm_tc_kernel,
                             cudaFuncAttributeMaxDynamicSharedMemorySize, SM_TOTAL);
        attr_set = true;
    }

    embed_kernel<<<(M_DIM * H_DIM / 4) / 256, 256>>>(x, emb, h0);
    transpose_kernel<<<dim3(N_DIM / 32, K_DIM / 32, L_DIM), dim3(32, 8)>>>(W, Wt);

    dim3 ggrid(N_DIM / BN, M_DIM / BM);                // (24, 128)
    const int sgrid = (S_CHUNKS * NCH) / 256;          // 512 blocks x 256

    gemm_tc_kernel<<<ggrid, 256, SM_TOTAL>>>(h0, Wt + 0 * (size_t)N_DIM * K_DIM,
                                             bias + 0 * N_DIM, G);
    scan_pass1<<<sgrid, 256>>>(G, P, Q);
    scan_pass2<<<sgrid, 256>>>(G, P, Q, nullptr, h1, T_DIM, 1);

    gemm_tc_kernel<<<ggrid, 256, SM_TOTAL>>>(h1, Wt + 1 * (size_t)N_DIM * K_DIM,
                                             bias + 1 * N_DIM, G);
    scan_pass1<<<sgrid, 256>>>(G, P, Q);
    scan_pass2<<<sgrid, 256>>>(G, P, Q, nullptr, h0, T_DIM, 1);

    gemm_tc_kernel<<<ggrid, 256, SM_TOTAL>>>(h0, Wt + 2 * (size_t)N_DIM * K_DIM,
                                             bias + 2 * N_DIM, G);
    scan_pass1<<<sgrid, 256>>>(G, P, Q);
    scan_pass2<<<sgrid, 256>>>(G, P, Q, out, nullptr, T_DIM - 1, 0);
}

// round 7
// speedup vs baseline: 6.9857x; 1.2327x over previous
#include <cuda_runtime.h>
#include <cuda_fp16.h>
#include <cstdint>
#include <math.h>

// Problem dims
#define T_DIM 1024
#define B_DIM 16
#define H_DIM 1024
#define L_DIM 3
#define M_DIM (T_DIM * B_DIM)   // 16384
#define N_DIM (3 * H_DIM)       // 3072
#define K_DIM H_DIM             // 1024
#define NCH   (B_DIM * H_DIM)   // 16384 scan channels
#define NPAIR (NCH / 2)         // 8192 channel pairs

// GEMM tiling (fp16 operands, fp32 accum)
#define BM 128
#define BN 128
#define BK 64
#define K_ITERS (K_DIM / BK)     // 16
#define WM 64
#define WN 32
#define MT (WM / 16)
#define NT (WN / 8)
#define ROWB 144                 // bytes per SMEM row (72 halves, padded)
#define TILE_BYTES (128 * ROWB)
#define STAGE_BYTES (2 * TILE_BYTES)
#define STAGES 3
#define SM_TOTAL (STAGES * STAGE_BYTES)    // 110592

// Scan chunking
#define S_CHUNKS 16
#define CHUNK_T (T_DIM / S_CHUNKS)  // 64

// Scratch (device globals, no runtime alloc)
__device__ __half g_h0[(size_t)M_DIM * H_DIM];
__device__ __half g_h1[(size_t)M_DIM * H_DIM];
__device__ __half g_G [(size_t)M_DIM * N_DIM];
__device__ __half g_Wt[(size_t)L_DIM * N_DIM * K_DIM];
__device__ float  g_P [(size_t)S_CHUNKS * NCH];
__device__ float  g_Q [(size_t)S_CHUNKS * NCH];

// ---------------------------------------------------------------------------
// PTX helpers (sm_80-era only; compute_103 target rejects tcgen05)
// ---------------------------------------------------------------------------
__device__ __forceinline__ uint32_t smem_to_u32(const void* p) {
    uint32_t a;
    asm("{ .reg .u64 t; cvta.to.shared.u64 t, %1; cvt.u32.u64 %0, t; }" : "=r"(a) : "l"(p));
    return a;
}
#define CP_ASYNC16(sa, gp) \
    asm volatile("cp.async.cg.shared.global [%0], [%1], 16;" :: "r"(sa), "l"(gp))
#define CP_COMMIT() asm volatile("cp.async.commit_group;" ::: "memory")
#define CP_WAIT1()  asm volatile("cp.async.wait_group 1;" ::: "memory")
#define CP_WAIT0()  asm volatile("cp.async.wait_group 0;" ::: "memory")

#define LDSM_X4(r0, r1, r2, r3, addr) \
    asm volatile("ldmatrix.sync.aligned.m8n8.x4.shared.b16 {%0,%1,%2,%3}, [%4];" \
                 : "=r"(r0), "=r"(r1), "=r"(r2), "=r"(r3) : "r"(addr))

__device__ __forceinline__ void mma_f16(float& c0, float& c1, float& c2, float& c3,
                                        uint32_t a0, uint32_t a1, uint32_t a2, uint32_t a3,
                                        uint32_t b0, uint32_t b1) {
    asm volatile("mma.sync.aligned.m16n8k16.row.col.f32.f16.f16.f32 "
                 "{%0,%1,%2,%3}, {%4,%5,%6,%7}, {%8,%9}, {%0,%1,%2,%3};"
                 : "+f"(c0), "+f"(c1), "+f"(c2), "+f"(c3)
                 : "r"(a0), "r"(a1), "r"(a2), "r"(a3), "r"(b0), "r"(b1));
}

// ---------------------------------------------------------------------------
// FMA-only activations (avoid MUFU pipe)
// ---------------------------------------------------------------------------
__device__ __forceinline__ float rcp_fma(float d) {
    float r = __int_as_float(0x7EF127EAu - __float_as_int(d));
    r = r * (2.0f - d * r);
    r = r * (2.0f - d * r);
    r = r * (2.0f - d * r);
    return r;
}
__device__ __forceinline__ float tanh_fast(float x) {
    x = fminf(fmaxf(x, -7.90531110f), 7.90531110f);
    float x2 = x * x;
    float p = -2.76076847742355e-16f;
    p = fmaf(p, x2, 2.00018790482477e-13f);
    p = fmaf(p, x2, -8.60467152213735e-11f);
    p = fmaf(p, x2, 5.12229709037114e-08f);
    p = fmaf(p, x2, 1.48572235717979e-05f);
    p = fmaf(p, x2, 6.37261928875436e-04f);
    p = fmaf(p, x2, 4.89352455891786e-03f);
    float q = 1.19825839466702e-06f;
    q = fmaf(q, x2, 1.18534705686654e-04f);
    q = fmaf(q, x2, 2.26843463243900e-03f);
    q = fmaf(q, x2, 4.89352518554385e-03f);
    return (x * p) * rcp_fma(q);
}
__device__ __forceinline__ float sigmoid_fast(float x) {
    return fmaf(0.5f, tanh_fast(0.5f * x), 0.5f);
}

// ---------------------------------------------------------------------------
// Embedding gather -> fp16 h buffer
// ---------------------------------------------------------------------------
__global__ void embed_kernel(const int* __restrict__ x,
                             const float* __restrict__ emb,
                             __half* __restrict__ h)
{
    int idx = blockIdx.x * blockDim.x + threadIdx.x;
    int i   = idx * 4;
    int tb  = i >> 10;
    int hh  = i & (H_DIM - 1);
    int tok = x[tb];
    float4 v = *(const float4*)(emb + (size_t)tok * H_DIM + hh);
    __half2 lo = __floats2half2_rn(v.x, v.y);
    __half2 hi = __floats2half2_rn(v.z, v.w);
    uint2 pk = { *(uint32_t*)&lo, *(uint32_t*)&hi };
    *(uint2*)(h + i) = pk;
}

// ---------------------------------------------------------------------------
// W transpose + fp16 round:  Wt[l][n][k] = half(W[l][k][n])
// ---------------------------------------------------------------------------
__global__ void transpose_kernel(const float* __restrict__ W, __half* __restrict__ Wt)
{
    __shared__ float tile[32][33];
    int l  = blockIdx.z;
    int n0 = blockIdx.x * 32;
    int k0 = blockIdx.y * 32;
    int tx = threadIdx.x, ty = threadIdx.y;
    #pragma unroll
    for (int j = 0; j < 32; j += 8) {
        int k = k0 + ty + j, n = n0 + tx;
        tile[ty + j][tx] = W[((size_t)l * K_DIM + k) * N_DIM + n];
    }
    __syncthreads();
    #pragma unroll
    for (int j = 0; j < 32; j += 8) {
        int n = n0 + ty + j, k = k0 + tx;
        Wt[((size_t)l * N_DIM + n) * K_DIM + k] = __float2half_rn(tile[tx][ty + j]);
    }
}

// ---------------------------------------------------------------------------
// FP16 tensor-core GEMM: mma.sync m16n8k16 + ldmatrix + 3-stage cp.async.
//   G[M,N] = act( A[M,K] @ Wt[N,K]^T + bias[N] ),  G stored fp16
// ---------------------------------------------------------------------------
__global__ __launch_bounds__(256, 2)
void gemm_tc_kernel(const __half* __restrict__ A,
                    const __half* __restrict__ Bt,
                    const float* __restrict__ bias,
                    __half* __restrict__ C)
{
    extern __shared__ char smem[];

    const int tid = threadIdx.x;
    const int wid = tid >> 5;
    const int lid = tid & 31;
    const int g   = lid >> 2;
    const int t   = lid & 3;
    const int bm  = blockIdx.y * BM;
    const int bn  = blockIdx.x * BN;
    const int wm  = (wid >> 2) * WM;
    const int wn  = (wid & 3) * WN;

    const int l_row = tid >> 3;
    const int l_cir = tid & 7;
    const __half* Ag = A  + (size_t)(bm + l_row) * K_DIM + l_cir * 8;
    const __half* Bg = Bt + (size_t)(bn + l_row) * K_DIM + l_cir * 8;
    const uint32_t smem_base = smem_to_u32(smem);
    const uint32_t sAo = smem_base + l_row * ROWB + l_cir * 16;
    const uint32_t sBo = sAo + TILE_BYTES;

    const int r8 = lid & 7;
    const int q  = lid >> 3;
    uint32_t aoff[MT], boff[NT / 2];
    #pragma unroll
    for (int mt = 0; mt < MT; mt++)
        aoff[mt] = (uint32_t)((wm + mt * 16 + r8 + (q & 1) * 8) * ROWB + (q >> 1) * 16);
    #pragma unroll
    for (int p = 0; p < NT / 2; p++)
        boff[p] = (uint32_t)(TILE_BYTES + (wn + p * 16 + r8 + (q >> 1) * 8) * ROWB
                             + (q & 1) * 16);

    float acc[MT][NT][4];
    #pragma unroll
    for (int i = 0; i < MT; i++)
        #pragma unroll
        for (int j = 0; j < NT; j++)
            #pragma unroll
            for (int r = 0; r < 4; r++) acc[i][j][r] = 0.0f;

    #pragma unroll
    for (int p = 0; p < 2; p++) {
        const uint32_t soff = p * STAGE_BYTES;
        const __half* Ak = Ag + p * BK;
        const __half* Bk = Bg + p * BK;
        #pragma unroll
        for (int j = 0; j < 4; j++) {
            CP_ASYNC16(sAo + soff + j * 32 * ROWB, Ak + (size_t)(j * 32) * K_DIM);
            CP_ASYNC16(sBo + soff + j * 32 * ROWB, Bk + (size_t)(j * 32) * K_DIM);
        }
        CP_COMMIT();
    }

    int stg = 0, wst = 2;
    for (int i = 0; i < K_ITERS; i++) {
        if (i + 1 < K_ITERS) CP_WAIT1(); else CP_WAIT0();
        __syncthreads();

        if (i + 2 < K_ITERS) {
            const uint32_t soff = wst * STAGE_BYTES;
            const __half* Ak = Ag + (i + 2) * BK;
            const __half* Bk = Bg + (i + 2) * BK;
            #pragma unroll
            for (int j = 0; j < 4; j++) {
                CP_ASYNC16(sAo + soff + j * 32 * ROWB, Ak + (size_t)(j * 32) * K_DIM);
                CP_ASYNC16(sBo + soff + j * 32 * ROWB, Bk + (size_t)(j * 32) * K_DIM);
            }
            CP_COMMIT();
        }

        const uint32_t sbase = smem_base + stg * STAGE_BYTES;
        #pragma unroll
        for (int ks = 0; ks < 4; ks++) {
            const uint32_t kb = ks * 32;
            uint32_t af[MT][4], bf[NT][2];
            #pragma unroll
            for (int mt = 0; mt < MT; mt++)
                LDSM_X4(af[mt][0], af[mt][1], af[mt][2], af[mt][3],
                        sbase + aoff[mt] + kb);
            #pragma unroll
            for (int p = 0; p < NT / 2; p++)
                LDSM_X4(bf[2 * p][0], bf[2 * p][1], bf[2 * p + 1][0], bf[2 * p + 1][1],
                        sbase + boff[p] + kb);
            #pragma unroll
            for (int mt = 0; mt < MT; mt++)
                #pragma unroll
                for (int nt = 0; nt < NT; nt++)
                    mma_f16(acc[mt][nt][0], acc[mt][nt][1],
                            acc[mt][nt][2], acc[mt][nt][3],
                            af[mt][0], af[mt][1], af[mt][2], af[mt][3],
                            bf[nt][0], bf[nt][1]);
        }

        stg = (stg == 2) ? 0 : stg + 1;
        wst = (wst == 2) ? 0 : wst + 1;
    }

    // epilogue: bias + activation, half2 stores
    #pragma unroll
    for (int mt = 0; mt < MT; mt++) {
        const int row0 = bm + wm + mt * 16 + g;
        #pragma unroll
        for (int nt = 0; nt < NT; nt++) {
            const int col = bn + wn + nt * 8 + 2 * t;
            const float b0 = __ldg(&bias[col]);
            const float b1 = __ldg(&bias[col + 1]);
            float2 v0, v1;
            if (col < H_DIM) {
                v0.x = tanh_fast(acc[mt][nt][0] + b0);
                v0.y = tanh_fast(acc[mt][nt][1] + b1);
                v1.x = tanh_fast(acc[mt][nt][2] + b0);
                v1.y = tanh_fast(acc[mt][nt][3] + b1);
            } else {
                v0.x = sigmoid_fast(acc[mt][nt][0] + b0);
                v0.y = sigmoid_fast(acc[mt][nt][1] + b1);
                v1.x = sigmoid_fast(acc[mt][nt][2] + b0);
                v1.y = sigmoid_fast(acc[mt][nt][3] + b1);
            }
            *(__half2*)&C[(size_t)row0 * N_DIM + col]       = __floats2half2_rn(v0.x, v0.y);
            *(__half2*)&C[(size_t)(row0 + 8) * N_DIM + col] = __floats2half2_rn(v1.x, v1.y);
        }
    }
}

// ---------------------------------------------------------------------------
// Chunked-parallel forget-mult scan over fp16 gates, half2 channel pairs.
// pass1: per-chunk affine map (P = prod(1-f), Q = chunk scan from 0).
// ---------------------------------------------------------------------------
__global__ void scan_pass1(const __half* __restrict__ G,
                           float* __restrict__ P, float* __restrict__ Q)
{
    const int id = blockIdx.x * blockDim.x + threadIdx.x;   // 0 .. S*NPAIR-1
    const int j2 = id & (NPAIR - 1);
    const int s  = id >> 13;
    const int b  = j2 >> 9;                 // pair index / (H/2)
    const int hh = (j2 & 511) * 2;
    const __half* gz = G + ((size_t)(s * CHUNK_T) * B_DIM + b) * N_DIM + hh;

    float2 c = {0.0f, 0.0f}, p = {1.0f, 1.0f};
    #pragma unroll 8
    for (int t = 0; t < CHUNK_T; t++) {
        const __half* ptr = gz + (size_t)t * (B_DIM * N_DIM);
        float2 z = __half22float2(*(const __half2*)(ptr));
        float2 f = __half22float2(*(const __half2*)(ptr + H_DIM));
        c.x = fmaf(f.x, z.x - c.x, c.x);
        c.y = fmaf(f.y, z.y - c.y, c.y);
        p.x *= (1.0f - f.x);
        p.y *= (1.0f - f.y);
    }
    *(float2*)&P[(size_t)s * NCH + 2 * j2] = p;
    *(float2*)&Q[(size_t)s * NCH + 2 * j2] = c;
}

// pass2: combine predecessor maps, rescan, emit o*c
__global__ void scan_pass2(const __half* __restrict__ G,
                           const float* __restrict__ P, const float* __restrict__ Q,
                           float* __restrict__ outf, __half* __restrict__ outh,
                           int Tout, int write_half)
{
    const int id = blockIdx.x * blockDim.x + threadIdx.x;
    const int j2 = id & (NPAIR - 1);
    const int s  = id >> 13;
    const int b  = j2 >> 9;
    const int hh = (j2 & 511) * 2;

    float2 c = {0.0f, 0.0f};
    for (int ss = 0; ss < s; ss++) {
        float2 p2 = *(const float2*)&P[(size_t)ss * NCH + 2 * j2];
        float2 q2 = *(const float2*)&Q[(size_t)ss * NCH + 2 * j2];
        c.x = fmaf(p2.x, c.x, q2.x);
        c.y = fmaf(p2.y, c.y, q2.y);
    }

    const __half* gz = G + ((size_t)(s * CHUNK_T) * B_DIM + b) * N_DIM + hh;
    const size_t obase = ((size_t)(s * CHUNK_T) * B_DIM + b) * H_DIM + hh;
    const int tmax = Tout - s * CHUNK_T;
    #pragma unroll 8
    for (int t = 0; t < CHUNK_T; t++) {
        const __half* ptr = gz + (size_t)t * (B_DIM * N_DIM);
        float2 z = __half22float2(*(const __half2*)(ptr));
        float2 f = __half22float2(*(const __half2*)(ptr + H_DIM));
        float2 o = __half22float2(*(const __half2*)(ptr + 2 * H_DIM));
        c.x = fmaf(f.x, z.x - c.x, c.x);
        c.y = fmaf(f.y, z.y - c.y, c.y);
        if (t < tmax) {
            const size_t oi = obase + (size_t)t * (B_DIM * H_DIM);
            if (write_half)
                *(__half2*)&outh[oi] = __floats2half2_rn(o.x * c.x, o.y * c.y);
            else
                *(float2*)&outf[oi] = make_float2(o.x * c.x, o.y * c.y);
        }
    }
}

// ---------------------------------------------------------------------------
extern "C" void kernel_launch(void* const* d_in, const int* in_sizes, int n_in,
                              void* d_out, int out_size)
{
    const int*   x    = (const int*)  d_in[0];
    const float* emb  = (const float*)d_in[1];
    const float* W    = (const float*)d_in[2];
    const float* bias = (const float*)d_in[3];
    float* out = (float*)d_out;

    __half *h0, *h1, *Wt, *G;
    float *P, *Q;
    cudaGetSymbolAddress((void**)&h0, g_h0);
    cudaGetSymbolAddress((void**)&h1, g_h1);
    cudaGetSymbolAddress((void**)&G,  g_G);
    cudaGetSymbolAddress((void**)&Wt, g_Wt);
    cudaGetSymbolAddress((void**)&P,  g_P);
    cudaGetSymbolAddress((void**)&Q,  g_Q);

    static bool attr_set = false;
    if (!attr_set) {
        cudaFuncSetAttribute(gemm_tc_kernel,
                             cudaFuncAttributeMaxDynamicSharedMemorySize, SM_TOTAL);
        attr_set = true;
    }

    embed_kernel<<<(M_DIM * H_DIM / 4) / 256, 256>>>(x, emb, h0);
    transpose_kernel<<<dim3(N_DIM / 32, K_DIM / 32, L_DIM), dim3(32, 8)>>>(W, Wt);

    dim3 ggrid(N_DIM / BN, M_DIM / BM);                 // (24, 128)
    const int sgrid = (S_CHUNKS * NPAIR) / 256;         // 512 blocks x 256

    gemm_tc_kernel<<<ggrid, 256, SM_TOTAL>>>(h0, Wt + 0 * (size_t)N_DIM * K_DIM,
                                             bias + 0 * N_DIM, G);
    scan_pass1<<<sgrid, 256>>>(G, P, Q);
    scan_pass2<<<sgrid, 256>>>(G, P, Q, nullptr, h1, T_DIM, 1);

    gemm_tc_kernel<<<ggrid, 256, SM_TOTAL>>>(h1, Wt + 1 * (size_t)N_DIM * K_DIM,
                                             bias + 1 * N_DIM, G);
    scan_pass1<<<sgrid, 256>>>(G, P, Q);
    scan_pass2<<<sgrid, 256>>>(G, P, Q, nullptr, h0, T_DIM, 1);

    gemm_tc_kernel<<<ggrid, 256, SM_TOTAL>>>(h0, Wt + 2 * (size_t)N_DIM * K_DIM,
                                             bias + 2 * N_DIM, G);
    scan_pass1<<<sgrid, 256>>>(G, P, Q);
    scan_pass2<<<sgrid, 256>>>(G, P, Q, out, nullptr, T_DIM - 1, 0);
}